// round 15
// baseline (speedup 1.0000x reference)
#include <cuda_runtime.h>
#include <cuda_fp16.h>

#define NTHREADS 256
#define GPB 128           // graphs per block
#define GPT 4             // graphs per thread (conv phase)

#define SLOT_W 68         // 32-bit words per graph slot (128 halfs + pad)
#define W1_W 68           // words per Wl1 row
#define W2_W 36           // words per Wl2 row

// smem layout in 32-bit words. Edges + conv features + flat + z all live in HS slots.
#define SM_HS 0
#define SM_W1 (GPB * SLOT_W)              // 8704
#define SM_W2 (SM_W1 + 64 * W1_W)         // 13056
#define SM_W3H (SM_W2 + 16 * W2_W)        // 13632  (W3 as fp16: 64 words, pos = c*4 + kw)
#define SMEM_WORDS (SM_W3H + 64)          // 13696
#define SMEM_BYTES (SMEM_WORDS * 4)       // 54784 B -> 4 blocks/SM (219KB of 228KB)

// offsets into cAll (floats). W1/W2 segments hold PAIR-TRANSPOSED layout:
//   pos = cp*(2*K) + k*2 + r  <=>  W[(2*cp + r)][k]
#define CW_W1 0
#define CW_B1 8
#define CW_W2 12
#define CW_B2 44
#define CW_W3 52
#define CW_B3 180
#define CW_BL1 196
#define CW_BL2 260

__constant__ __align__(16) float cAll[288];
__device__ float g_stage[288];

typedef unsigned long long u64;

__device__ __forceinline__ u64 fma2(u64 a, u64 b, u64 c) {
    u64 d;
    asm("fma.rn.f32x2 %0, %1, %2, %3;" : "=l"(d) : "l"(a), "l"(b), "l"(c));
    return d;
}
__device__ __forceinline__ u64 pack2(float lo, float hi) {
    u64 d; asm("mov.b64 %0, {%1, %2};" : "=l"(d) : "f"(lo), "f"(hi)); return d;
}
__device__ __forceinline__ float2 unpack2(u64 v) {
    float2 r; asm("mov.b64 {%0, %1}, %2;" : "=f"(r.x), "=f"(r.y) : "l"(v)); return r;
}
__device__ __forceinline__ __half2 u2h2(unsigned u) { return *(__half2*)&u; }
__device__ __forceinline__ unsigned h22u(__half2 h) { return *(unsigned*)&h; }

// count byte (0..16) -> broadcast half2
__device__ __forceinline__ __half2 cnt2(unsigned wd, int m) {
    unsigned b = (wd >> (8 * m)) & 0xFFu;
    return __half2half2(__ushort2half_rn((unsigned short)b));
}

// fp16 mma m16n8k16: D(16x8,f32) += A(16x16,f16) * B(16x8,f16)
__device__ __forceinline__ void mma_f16(float d[4],
    unsigned a0, unsigned a1, unsigned a2, unsigned a3,
    unsigned b0, unsigned b1)
{
    asm("mma.sync.aligned.m16n8k16.row.col.f32.f16.f16.f32 "
        "{%0,%1,%2,%3}, {%4,%5,%6,%7}, {%8,%9}, {%0,%1,%2,%3};"
        : "+f"(d[0]), "+f"(d[1]), "+f"(d[2]), "+f"(d[3])
        : "r"(a0), "r"(a1), "r"(a2), "r"(a3), "r"(b0), "r"(b1));
}
// fp16 mma m16n8k8: D(16x8,f32) += A(16x8,f16) * B(8x8,f16)
__device__ __forceinline__ void mma_f16_k8(float d[4],
    unsigned a0, unsigned a1, unsigned b0)
{
    asm("mma.sync.aligned.m16n8k8.row.col.f32.f16.f16.f32 "
        "{%0,%1,%2,%3}, {%4,%5}, {%6}, {%0,%1,%2,%3};"
        : "+f"(d[0]), "+f"(d[1]), "+f"(d[2]), "+f"(d[3])
        : "r"(a0), "r"(a1), "r"(b0));
}

// pack the 8 small weight arrays into one contiguous device buffer (1 block).
// W1/W2/W3 are written PAIR-TRANSPOSED: pos = cp*2K + 2k + r  <- W[(2cp+r)][k]
__global__ void gather_weights(const float* __restrict__ W1, const float* __restrict__ b1,
                               const float* __restrict__ W2, const float* __restrict__ b2,
                               const float* __restrict__ W3, const float* __restrict__ b3,
                               const float* __restrict__ bl1, const float* __restrict__ bl2)
{
    int t = threadIdx.x;
    float v = 0.f;
    if (t < 8) {                      // W1: 4x2, K=2
        int u = t, cp = u >> 2, rm = u & 3, k = rm >> 1, r = rm & 1;
        v = W1[(2 * cp + r) * 2 + k];
    } else if (t < 12)  v = b1[t - CW_B1];
    else if (t < 44) {                // W2: 8x4, K=4
        int u = t - CW_W2, cp = u >> 3, rm = u & 7, k = rm >> 1, r = rm & 1;
        v = W2[(2 * cp + r) * 4 + k];
    } else if (t < 52)  v = b2[t - CW_B2];
    else if (t < 180) {               // W3 (unused by kernel now, kept for layout stability)
        int u = t - CW_W3, cp = u >> 4, rm = u & 15, k = rm >> 1, r = rm & 1;
        v = W3[(2 * cp + r) * 8 + k];
    } else if (t < 196) v = b3[t - CW_B3];
    else if (t < 260) v = bl1[t - CW_BL1];
    else if (t < 276) v = bl2[t - CW_BL2];
    g_stage[t] = v;
}

__global__ __launch_bounds__(NTHREADS, 4)
void gnn_kernel(const float* __restrict__ x, const int* __restrict__ ei,
                const float* __restrict__ Wl1, const float* __restrict__ Wl2,
                const float* __restrict__ W3g,
                float* __restrict__ out, int B)
{
    extern __shared__ float smf[];
    unsigned* smw = (unsigned*)smf;

    const int tid  = threadIdx.x;
    const int q    = tid >> 3;     // slot 0..31 (conv phase; +32j for graph j)
    const int n    = tid & 7;      // node 0..7
    const int lane = tid & 31;
    const int w    = tid >> 5;     // warp 0..7
    const int gbase = blockIdx.x * GPB;

    // ---- stage Wl1/Wl2 as fp16
#pragma unroll
    for (int i = 0; i < 8; i++) {
        int idx = tid + i * NTHREADS;           // 0..2047 float4s of Wl1 (64x128)
        int r = idx >> 5, kk = idx & 31;
        float4 v = ((const float4*)Wl1)[r * 32 + kk];
        uint2 p;
        p.x = h22u(__floats2half2_rn(v.x, v.y));
        p.y = h22u(__floats2half2_rn(v.z, v.w));
        *(uint2*)(smw + SM_W1 + r * W1_W + 2 * kk) = p;
    }
    {
        int r = tid >> 4, kk = tid & 15;        // Wl2 16x64
        float4 v = ((const float4*)Wl2)[r * 16 + kk];
        uint2 p;
        p.x = h22u(__floats2half2_rn(v.x, v.y));
        p.y = h22u(__floats2half2_rn(v.z, v.w));
        *(uint2*)(smw + SM_W2 + r * W2_W + 2 * kk) = p;
    }
    // ---- stage W3 as fp16 for conv-3 mma: pos = c*4 + kw  (c=row 0..15, kw=k-word 0..3)
    if (tid < 32) {
        float4 v = ((const float4*)W3g)[tid];      // W3[c][4ks..4ks+3], c=tid>>1, ks=tid&1
        int c = tid >> 1, ks = tid & 1;
        smw[SM_W3H + c * 4 + 2 * ks]     = h22u(__floats2half2_rn(v.x, v.y));
        smw[SM_W3H + c * 4 + 2 * ks + 1] = h22u(__floats2half2_rn(v.z, v.w));
    }

    // ---- stage edges WARP-LOCALLY into own slots (stride SLOT_W ints)
    int* esI = (int*)smw;
#pragma unroll
    for (int j = 0; j < GPT; j++) {
        int slot = 4 * w + (lane >> 3) + 32 * j;
        int g = gbase + slot; if (g >= B) g = B - 1;
        int v = lane & 7;
        *(int4*)(esI + slot * SLOT_W + v * 4) = ((const int4*)ei)[g * 8 + v];
    }
    // ---- load x for my graphs
    float h0[GPT][2];
#pragma unroll
    for (int j = 0; j < GPT; j++) {
        int g = gbase + q + 32 * j; if (g >= B) g = B - 1;
        float2 xv = ((const float2*)x)[g * 8 + n];
        h0[j][0] = xv.x; h0[j][1] = xv.y;
    }
    __syncthreads();   // W3h visible to all warps before conv-3 mma

    // ---- adjacency byte-counts (self-loop folded) + degree (warp-local reads)
    unsigned c0[GPT], c1[GPT]; float dis[GPT];
#pragma unroll
    for (int j = 0; j < GPT; j++) {
        const int4* eg = (const int4*)(esI + (q + 32 * j) * SLOT_W);
        unsigned a0 = 0, a1 = 0;
#pragma unroll
        for (int e4 = 0; e4 < 4; e4++) {
            int4 rv = eg[e4];        // rows
            int4 cv = eg[4 + e4];    // cols
            {unsigned inc = (unsigned)(cv.x == n) << (8 * (rv.x & 3)); if (rv.x < 4) a0 += inc; else a1 += inc;}
            {unsigned inc = (unsigned)(cv.y == n) << (8 * (rv.y & 3)); if (rv.y < 4) a0 += inc; else a1 += inc;}
            {unsigned inc = (unsigned)(cv.z == n) << (8 * (rv.z & 3)); if (rv.z < 4) a0 += inc; else a1 += inc;}
            {unsigned inc = (unsigned)(cv.w == n) << (8 * (rv.w & 3)); if (rv.w < 4) a0 += inc; else a1 += inc;}
        }
        if (n < 4) a0 += 1u << (8 * n); else a1 += 1u << (8 * (n - 4));
        unsigned deg = __dp4a(a0, 0x01010101u, __dp4a(a1, 0x01010101u, 0u));
        dis[j] = rsqrtf((float)deg);
        c0[j] = a0; c1[j] = a1;
    }
    __syncwarp();    // edge reads done before publishes overwrite the slot words

    // ================= conv layer 1 (Cin=2 -> Cout=4) =================
#pragma unroll
    for (int j = 0; j < GPT; j++)
        smw[(q + 32 * j) * SLOT_W + 8 * n] =
            h22u(__floats2half2_rn(h0[j][0] * dis[j], h0[j][1] * dis[j]));
    __syncwarp();

    __half2 acc1[GPT];
#pragma unroll
    for (int j = 0; j < GPT; j++) {
        __half2 acc = __float2half2_rn(0.f);
        const unsigned* hg = smw + (q + 32 * j) * SLOT_W;
#pragma unroll
        for (int m = 0; m < 8; m++) {
            __half2 cw = (m < 4) ? cnt2(c0[j], m) : cnt2(c1[j], m - 4);
            acc = __hfma2(cw, u2h2(hg[8 * m]), acc);
        }
        acc1[j] = acc;
    }
    __syncwarp();

    // matmul W1 (packed f32x2 pairs) + bias + relu + *dis, publish h1*dis
#pragma unroll
    for (int j = 0; j < GPT; j++) {
        float2 a = __half22float2(acc1[j]);
        u64 axx = pack2(a.x, a.x), ayy = pack2(a.y, a.y);
        u64 dd  = pack2(dis[j], dis[j]);
        float t[4];
#pragma unroll
        for (int cp = 0; cp < 2; cp++) {
            u64 s = fma2(*(const u64*)&cAll[CW_W1 + cp * 4], axx, 0ull);
            s = fma2(*(const u64*)&cAll[CW_W1 + cp * 4 + 2], ayy, s);
            s = fma2(dd, s, *(const u64*)&cAll[CW_B1 + 2 * cp]);
            float2 f = unpack2(s);
            t[2 * cp]     = fmaxf(f.x, 0.f) * dis[j];
            t[2 * cp + 1] = fmaxf(f.y, 0.f) * dis[j];
        }
        uint2 p;
        p.x = h22u(__floats2half2_rn(t[0], t[1]));
        p.y = h22u(__floats2half2_rn(t[2], t[3]));
        *(uint2*)(smw + (q + 32 * j) * SLOT_W + 8 * n) = p;
    }
    __syncwarp();

    // ================= conv layer 2 (Cin=4 -> Cout=8) =================
    __half2 acc2[GPT][2];
#pragma unroll
    for (int j = 0; j < GPT; j++) {
        __half2 s0 = __float2half2_rn(0.f), s1 = s0;
        const unsigned* hg = smw + (q + 32 * j) * SLOT_W;
#pragma unroll
        for (int m = 0; m < 8; m++) {
            __half2 cw = (m < 4) ? cnt2(c0[j], m) : cnt2(c1[j], m - 4);
            uint2 v = *(const uint2*)(hg + 8 * m);
            s0 = __hfma2(cw, u2h2(v.x), s0);
            s1 = __hfma2(cw, u2h2(v.y), s1);
        }
        acc2[j][0] = s0; acc2[j][1] = s1;
    }
    __syncwarp();

#pragma unroll
    for (int j = 0; j < GPT; j++) {
        float2 a01 = __half22float2(acc2[j][0]);
        float2 a23 = __half22float2(acc2[j][1]);
        u64 ab[4] = { pack2(a01.x, a01.x), pack2(a01.y, a01.y),
                      pack2(a23.x, a23.x), pack2(a23.y, a23.y) };
        u64 dd = pack2(dis[j], dis[j]);
        unsigned pw[4];
#pragma unroll
        for (int cp = 0; cp < 4; cp++) {
            u64 s = 0ull;
#pragma unroll
            for (int k = 0; k < 4; k++)
                s = fma2(*(const u64*)&cAll[CW_W2 + cp * 8 + 2 * k], ab[k], s);
            s = fma2(dd, s, *(const u64*)&cAll[CW_B2 + 2 * cp]);
            float2 f = unpack2(s);
            pw[cp] = h22u(__floats2half2_rn(fmaxf(f.x, 0.f) * dis[j],
                                            fmaxf(f.y, 0.f) * dis[j]));
        }
        *(uint4*)(smw + (q + 32 * j) * SLOT_W + 8 * n) =
            make_uint4(pw[0], pw[1], pw[2], pw[3]);
    }
    __syncwarp();

    // ================= conv layer 3 (Cin=8 -> Cout=16) via mma =================
    __half2 acc3[GPT][4];
#pragma unroll
    for (int j = 0; j < GPT; j++) {
        __half2 s0 = __float2half2_rn(0.f), s1 = s0, s2 = s0, s3 = s0;
        const unsigned* hg = smw + (q + 32 * j) * SLOT_W;
#pragma unroll
        for (int m = 0; m < 8; m++) {
            __half2 cw = (m < 4) ? cnt2(c0[j], m) : cnt2(c1[j], m - 4);
            uint4 v = *(const uint4*)(hg + 8 * m);
            s0 = __hfma2(cw, u2h2(v.x), s0);
            s1 = __hfma2(cw, u2h2(v.y), s1);
            s2 = __hfma2(cw, u2h2(v.z), s2);
            s3 = __hfma2(cw, u2h2(v.w), s3);
        }
        acc3[j][0] = s0; acc3[j][1] = s1; acc3[j][2] = s2; acc3[j][3] = s3;
    }
    __syncwarp();

    // scale by dis (fp16, per-row = per-thread) and store A operand (4 words/graph)
#pragma unroll
    for (int j = 0; j < GPT; j++) {
        __half2 d2 = __float2half2_rn(dis[j]);
        uint4 st;
        st.x = h22u(__hmul2(acc3[j][0], d2));
        st.y = h22u(__hmul2(acc3[j][1], d2));
        st.z = h22u(__hmul2(acc3[j][2], d2));
        st.w = h22u(__hmul2(acc3[j][3], d2));
        *(uint4*)(smw + (q + 32 * j) * SLOT_W + 8 * n) = st;
    }
    __syncwarp();

    // mma over the warp's 16 graphs: 8 M-tiles (2 graphs each) x 2 N-tiles
    {
        const int grp = lane >> 2;   // 0..7 (= node / output row within tile)
        const int qd  = lane & 3;    // 0..3 (= k-word / channel-pair)
        unsigned b0 = smw[SM_W3H + grp * 4 + qd];        // B cols 0..7  (W3 rows grp)
        unsigned b1 = smw[SM_W3H + (grp + 8) * 4 + qd];  // B cols 8..15
        const float bA0 = cAll[CW_B3 + 2 * qd],     bA1 = cAll[CW_B3 + 2 * qd + 1];
        const float bB0 = cAll[CW_B3 + 8 + 2 * qd], bB1 = cAll[CW_B3 + 9 + 2 * qd];
#pragma unroll
        for (int t = 0; t < 8; t++) {
            int g16a = 2 * t, g16b = 2 * t + 1;              // warp-local graph ids
            int s0 = 4 * w + (g16a & 3) + 32 * (g16a >> 2);  // slot indices
            int s1 = 4 * w + (g16b & 3) + 32 * (g16b >> 2);
            unsigned a0 = smw[s0 * SLOT_W + 8 * grp + qd];   // row grp   (graph g16a)
            unsigned a1 = smw[s1 * SLOT_W + 8 * grp + qd];   // row grp+8 (graph g16b)
            float e0[4] = { bA0, bA1, bA0, bA1 };
            float e1[4] = { bB0, bB1, bB0, bB1 };
            mma_f16_k8(e0, a0, a1, b0);
            mma_f16_k8(e1, a0, a1, b1);
            smw[s0 * SLOT_W + 8 * grp + qd] =
                h22u(__floats2half2_rn(fmaxf(e0[0], 0.f), fmaxf(e0[1], 0.f)));
            smw[s0 * SLOT_W + 8 * grp + 4 + qd] =
                h22u(__floats2half2_rn(fmaxf(e1[0], 0.f), fmaxf(e1[1], 0.f)));
            smw[s1 * SLOT_W + 8 * grp + qd] =
                h22u(__floats2half2_rn(fmaxf(e0[2], 0.f), fmaxf(e0[3], 0.f)));
            smw[s1 * SLOT_W + 8 * grp + 4 + qd] =
                h22u(__floats2half2_rn(fmaxf(e1[2], 0.f), fmaxf(e1[3], 0.f)));
        }
    }

    __syncthreads();   // flat published; Wl1/Wl2 staged

    // ======== MLP1 via fp16 mma m16n8k16: warp w owns slots [16w, 16w+16)
    const int grp = lane >> 2;   // 0..7
    const int qd  = lane & 3;    // 0..3
    const unsigned* aBase = smw + (16 * w + grp) * SLOT_W + qd;
    const unsigned* bBase = smw + SM_W1 + grp * W1_W + qd;

    float d[8][4];
#pragma unroll
    for (int nt = 0; nt < 8; nt++) {
        float cc0 = cAll[CW_BL1 + nt * 8 + 2 * qd], cc1 = cAll[CW_BL1 + nt * 8 + 2 * qd + 1];
        d[nt][0] = cc0; d[nt][1] = cc1; d[nt][2] = cc0; d[nt][3] = cc1;
    }
#pragma unroll
    for (int kc = 0; kc < 8; kc++) {
        unsigned a0 = aBase[kc * 8];
        unsigned a1 = aBase[8 * SLOT_W + kc * 8];
        unsigned a2 = aBase[kc * 8 + 4];
        unsigned a3 = aBase[8 * SLOT_W + kc * 8 + 4];
#pragma unroll
        for (int nt = 0; nt < 8; nt++) {
            unsigned b0 = bBase[nt * 8 * W1_W + kc * 8];
            unsigned b1 = bBase[nt * 8 * W1_W + kc * 8 + 4];
            mma_f16(d[nt], a0, a1, a2, a3, b0, b1);
        }
    }
    __syncwarp();   // flat reads done before z overwrites slot words 0..31

    // relu + store z as halfs (64 halfs = words 0..31 of own slots)
    unsigned* z0 = smw + (16 * w + grp) * SLOT_W;
    unsigned* z1 = z0 + 8 * SLOT_W;
#pragma unroll
    for (int nt = 0; nt < 8; nt++) {
        z0[nt * 4 + qd] = h22u(__floats2half2_rn(fmaxf(d[nt][0], 0.f), fmaxf(d[nt][1], 0.f)));
        z1[nt * 4 + qd] = h22u(__floats2half2_rn(fmaxf(d[nt][2], 0.f), fmaxf(d[nt][3], 0.f)));
    }
    __syncwarp();

    // ======== MLP2 via fp16 mma: A = Z[16x64], B = Wl2[16x64]
    float e[2][4];
#pragma unroll
    for (int nt = 0; nt < 2; nt++) {
        float cc0 = cAll[CW_BL2 + nt * 8 + 2 * qd], cc1 = cAll[CW_BL2 + nt * 8 + 2 * qd + 1];
        e[nt][0] = cc0; e[nt][1] = cc1; e[nt][2] = cc0; e[nt][3] = cc1;
    }
    const unsigned* b2Base = smw + SM_W2 + grp * W2_W + qd;
#pragma unroll
    for (int kc = 0; kc < 4; kc++) {
        unsigned a0 = z0[kc * 8 + qd];
        unsigned a1 = z1[kc * 8 + qd];
        unsigned a2 = z0[kc * 8 + qd + 4];
        unsigned a3 = z1[kc * 8 + qd + 4];
#pragma unroll
        for (int nt = 0; nt < 2; nt++) {
            unsigned b0 = b2Base[nt * 8 * W2_W + kc * 8];
            unsigned b1 = b2Base[nt * 8 * W2_W + kc * 8 + 4];
            mma_f16(e[nt], a0, a1, a2, a3, b0, b1);
        }
    }
    // D fragments -> gmem (coalesced float2)
    const int g0 = gbase + 16 * w + grp;
#pragma unroll
    for (int nt = 0; nt < 2; nt++) {
        int col = nt * 8 + 2 * qd;
        if (g0 < B)
            *(float2*)(out + g0 * 16 + col) = make_float2(e[nt][0], e[nt][1]);
        if (g0 + 8 < B)
            *(float2*)(out + (g0 + 8) * 16 + col) = make_float2(e[nt][2], e[nt][3]);
    }
}

extern "C" void kernel_launch(void* const* d_in, const int* in_sizes, int n_in,
                              void* d_out, int out_size)
{
    const int B = in_sizes[0] / 16;   // x is [B, 8, 2]
    const int grid = (B + GPB - 1) / GPB;

    // 1) gather + pair-transpose the small weight arrays (1 node)
    gather_weights<<<1, 288>>>(
        (const float*)d_in[2], (const float*)d_in[3],
        (const float*)d_in[4], (const float*)d_in[5],
        (const float*)d_in[6], (const float*)d_in[7],
        (const float*)d_in[9], (const float*)d_in[11]);

    // 2) single D2D refresh of the constant bank (1 node)
    void* stagePtr = nullptr;
    cudaGetSymbolAddress(&stagePtr, g_stage);
    cudaMemcpyToSymbolAsync(cAll, stagePtr, 288 * sizeof(float), 0,
                            cudaMemcpyDeviceToDevice);

    // 3) main kernel
    cudaFuncSetAttribute(gnn_kernel, cudaFuncAttributeMaxDynamicSharedMemorySize, SMEM_BYTES);
    gnn_kernel<<<grid, NTHREADS, SMEM_BYTES>>>(
        (const float*)d_in[0], (const int*)d_in[1],
        (const float*)d_in[8], (const float*)d_in[10],
        (const float*)d_in[6],
        (float*)d_out, B);
}

// round 16
// speedup vs baseline: 1.0055x; 1.0055x over previous
#include <cuda_runtime.h>
#include <cuda_fp16.h>

#define NTHREADS 256
#define GPB 128           // graphs per block
#define GPT 4             // graphs per thread (conv phase)

#define SLOT_W 68         // 32-bit words per graph slot (128 halfs + pad)
#define W1_W 68           // words per Wl1 row
#define W2_W 36           // words per Wl2 row

// smem layout in 32-bit words. Edges + conv features + flat + z all live in HS slots.
#define SM_HS 0
#define SM_W1 (GPB * SLOT_W)              // 8704
#define SM_W2 (SM_W1 + 64 * W1_W)         // 13056
#define SM_W3H (SM_W2 + 16 * W2_W)        // 13632  (W3 as fp16: 64 words, pos = c*4 + kw)
#define SM_CW (SM_W3H + 64)               // 13696  (small weights, float region)
#define SMEM_WORDS (SM_CW + 288)          // 13984
#define SMEM_BYTES (SMEM_WORDS * 4)       // 55936 B -> 3 blocks/SM (167.8KB)

// offsets within CW (floats). W1/W2 segments hold PAIR-TRANSPOSED layout:
//   pos = cp*(2*K) + k*2 + r  <=>  W[(2*cp + r)][k]
#define CW_W1 0
#define CW_B1 8
#define CW_W2 12
#define CW_B2 44
#define CW_B3 180
#define CW_BL1 196
#define CW_BL2 260

typedef unsigned long long u64;

__device__ __forceinline__ u64 fma2(u64 a, u64 b, u64 c) {
    u64 d;
    asm("fma.rn.f32x2 %0, %1, %2, %3;" : "=l"(d) : "l"(a), "l"(b), "l"(c));
    return d;
}
__device__ __forceinline__ u64 pack2(float lo, float hi) {
    u64 d; asm("mov.b64 %0, {%1, %2};" : "=l"(d) : "f"(lo), "f"(hi)); return d;
}
__device__ __forceinline__ float2 unpack2(u64 v) {
    float2 r; asm("mov.b64 {%0, %1}, %2;" : "=f"(r.x), "=f"(r.y) : "l"(v)); return r;
}
__device__ __forceinline__ __half2 u2h2(unsigned u) { return *(__half2*)&u; }
__device__ __forceinline__ unsigned h22u(__half2 h) { return *(unsigned*)&h; }

// count byte (0..16) -> broadcast half2
__device__ __forceinline__ __half2 cnt2(unsigned wd, int m) {
    unsigned b = (wd >> (8 * m)) & 0xFFu;
    return __half2half2(__ushort2half_rn((unsigned short)b));
}

// fp16 mma m16n8k16: D(16x8,f32) += A(16x16,f16) * B(16x8,f16)
__device__ __forceinline__ void mma_f16(float d[4],
    unsigned a0, unsigned a1, unsigned a2, unsigned a3,
    unsigned b0, unsigned b1)
{
    asm("mma.sync.aligned.m16n8k16.row.col.f32.f16.f16.f32 "
        "{%0,%1,%2,%3}, {%4,%5,%6,%7}, {%8,%9}, {%0,%1,%2,%3};"
        : "+f"(d[0]), "+f"(d[1]), "+f"(d[2]), "+f"(d[3])
        : "r"(a0), "r"(a1), "r"(a2), "r"(a3), "r"(b0), "r"(b1));
}
// fp16 mma m16n8k8: D(16x8,f32) += A(16x8,f16) * B(8x8,f16)
__device__ __forceinline__ void mma_f16_k8(float d[4],
    unsigned a0, unsigned a1, unsigned b0)
{
    asm("mma.sync.aligned.m16n8k8.row.col.f32.f16.f16.f32 "
        "{%0,%1,%2,%3}, {%4,%5}, {%6}, {%0,%1,%2,%3};"
        : "+f"(d[0]), "+f"(d[1]), "+f"(d[2]), "+f"(d[3])
        : "r"(a0), "r"(a1), "r"(b0));
}

__global__ __launch_bounds__(NTHREADS, 3)
void gnn_kernel(const float* __restrict__ x, const int* __restrict__ ei,
                const float* __restrict__ Wl1, const float* __restrict__ Wl2,
                const float* __restrict__ W3g,
                const float* __restrict__ W1g, const float* __restrict__ b1g,
                const float* __restrict__ W2g, const float* __restrict__ b2g,
                const float* __restrict__ b3g,
                const float* __restrict__ bl1g, const float* __restrict__ bl2g,
                float* __restrict__ out, int B)
{
    extern __shared__ float smf[];
    unsigned* smw = (unsigned*)smf;
    float* cwS = smf + SM_CW;

    const int tid  = threadIdx.x;
    const int q    = tid >> 3;     // slot 0..31 (conv phase; +32j for graph j)
    const int n    = tid & 7;      // node 0..7
    const int lane = tid & 31;
    const int w    = tid >> 5;     // warp 0..7
    const int gbase = blockIdx.x * GPB;

    // ---- stage small weights/biases (pair-transposed W1/W2) into CW
    if (tid < 8) {                      // W1: 4x2, K=2 -> pair-transposed
        int cp = tid >> 2, rm = tid & 3, k = rm >> 1, r = rm & 1;
        cwS[CW_W1 + tid] = W1g[(2 * cp + r) * 2 + k];
    }
    if (tid >= 8 && tid < 12)   cwS[CW_B1 + tid - 8]  = b1g[tid - 8];
    if (tid >= 32 && tid < 64) {        // W2: 8x4, K=4 -> pair-transposed
        int u = tid - 32, cp = u >> 3, rm = u & 7, k = rm >> 1, r = rm & 1;
        cwS[CW_W2 + u] = W2g[(2 * cp + r) * 4 + k];
    }
    if (tid >= 64 && tid < 72)  cwS[CW_B2 + tid - 64]  = b2g[tid - 64];
    if (tid >= 96 && tid < 112) cwS[CW_B3 + tid - 96]  = b3g[tid - 96];
    if (tid >= 128 && tid < 192) cwS[CW_BL1 + tid - 128] = bl1g[tid - 128];
    if (tid >= 192 && tid < 208) cwS[CW_BL2 + tid - 192] = bl2g[tid - 192];

    // ---- stage Wl1/Wl2 as fp16
#pragma unroll
    for (int i = 0; i < 8; i++) {
        int idx = tid + i * NTHREADS;           // 0..2047 float4s of Wl1 (64x128)
        int r = idx >> 5, kk = idx & 31;
        float4 v = ((const float4*)Wl1)[r * 32 + kk];
        uint2 p;
        p.x = h22u(__floats2half2_rn(v.x, v.y));
        p.y = h22u(__floats2half2_rn(v.z, v.w));
        *(uint2*)(smw + SM_W1 + r * W1_W + 2 * kk) = p;
    }
    {
        int r = tid >> 4, kk = tid & 15;        // Wl2 16x64
        float4 v = ((const float4*)Wl2)[r * 16 + kk];
        uint2 p;
        p.x = h22u(__floats2half2_rn(v.x, v.y));
        p.y = h22u(__floats2half2_rn(v.z, v.w));
        *(uint2*)(smw + SM_W2 + r * W2_W + 2 * kk) = p;
    }
    // ---- stage W3 as fp16 for conv-3 mma: pos = c*4 + kw
    if (tid < 32) {
        float4 v = ((const float4*)W3g)[tid];      // W3[c][4ks..4ks+3], c=tid>>1, ks=tid&1
        int c = tid >> 1, ks = tid & 1;
        smw[SM_W3H + c * 4 + 2 * ks]     = h22u(__floats2half2_rn(v.x, v.y));
        smw[SM_W3H + c * 4 + 2 * ks + 1] = h22u(__floats2half2_rn(v.z, v.w));
    }

    // ---- stage edges WARP-LOCALLY into own slots (stride SLOT_W ints)
    int* esI = (int*)smw;
#pragma unroll
    for (int j = 0; j < GPT; j++) {
        int slot = 4 * w + (lane >> 3) + 32 * j;
        int g = gbase + slot; if (g >= B) g = B - 1;
        int v = lane & 7;
        *(int4*)(esI + slot * SLOT_W + v * 4) = ((const int4*)ei)[g * 8 + v];
    }
    // ---- load x for my graphs
    float h0[GPT][2];
#pragma unroll
    for (int j = 0; j < GPT; j++) {
        int g = gbase + q + 32 * j; if (g >= B) g = B - 1;
        float2 xv = ((const float2*)x)[g * 8 + n];
        h0[j][0] = xv.x; h0[j][1] = xv.y;
    }
    __syncthreads();   // CW + W3h staged, visible to all warps

    // ---- adjacency byte-counts (self-loop folded) + degree (warp-local reads)
    unsigned c0[GPT], c1[GPT]; float dis[GPT];
#pragma unroll
    for (int j = 0; j < GPT; j++) {
        const int4* eg = (const int4*)(esI + (q + 32 * j) * SLOT_W);
        unsigned a0 = 0, a1 = 0;
#pragma unroll
        for (int e4 = 0; e4 < 4; e4++) {
            int4 rv = eg[e4];        // rows
            int4 cv = eg[4 + e4];    // cols
            {unsigned inc = (unsigned)(cv.x == n) << (8 * (rv.x & 3)); if (rv.x < 4) a0 += inc; else a1 += inc;}
            {unsigned inc = (unsigned)(cv.y == n) << (8 * (rv.y & 3)); if (rv.y < 4) a0 += inc; else a1 += inc;}
            {unsigned inc = (unsigned)(cv.z == n) << (8 * (rv.z & 3)); if (rv.z < 4) a0 += inc; else a1 += inc;}
            {unsigned inc = (unsigned)(cv.w == n) << (8 * (rv.w & 3)); if (rv.w < 4) a0 += inc; else a1 += inc;}
        }
        if (n < 4) a0 += 1u << (8 * n); else a1 += 1u << (8 * (n - 4));
        unsigned deg = __dp4a(a0, 0x01010101u, __dp4a(a1, 0x01010101u, 0u));
        dis[j] = rsqrtf((float)deg);
        c0[j] = a0; c1[j] = a1;
    }
    __syncwarp();    // edge reads done before publishes overwrite the slot words

    // ================= conv layer 1 (Cin=2 -> Cout=4) =================
#pragma unroll
    for (int j = 0; j < GPT; j++)
        smw[(q + 32 * j) * SLOT_W + 8 * n] =
            h22u(__floats2half2_rn(h0[j][0] * dis[j], h0[j][1] * dis[j]));
    __syncwarp();

    __half2 acc1[GPT];
#pragma unroll
    for (int j = 0; j < GPT; j++) {
        __half2 acc = __float2half2_rn(0.f);
        const unsigned* hg = smw + (q + 32 * j) * SLOT_W;
#pragma unroll
        for (int m = 0; m < 8; m++) {
            __half2 cw = (m < 4) ? cnt2(c0[j], m) : cnt2(c1[j], m - 4);
            acc = __hfma2(cw, u2h2(hg[8 * m]), acc);
        }
        acc1[j] = acc;
    }
    __syncwarp();

    // matmul W1 (packed f32x2 pairs) + bias + relu + *dis, publish h1*dis
#pragma unroll
    for (int j = 0; j < GPT; j++) {
        float2 a = __half22float2(acc1[j]);
        u64 axx = pack2(a.x, a.x), ayy = pack2(a.y, a.y);
        u64 dd  = pack2(dis[j], dis[j]);
        float t[4];
#pragma unroll
        for (int cp = 0; cp < 2; cp++) {
            u64 s = fma2(*(const u64*)&cwS[CW_W1 + cp * 4], axx, 0ull);
            s = fma2(*(const u64*)&cwS[CW_W1 + cp * 4 + 2], ayy, s);
            s = fma2(dd, s, *(const u64*)&cwS[CW_B1 + 2 * cp]);
            float2 f = unpack2(s);
            t[2 * cp]     = fmaxf(f.x, 0.f) * dis[j];
            t[2 * cp + 1] = fmaxf(f.y, 0.f) * dis[j];
        }
        uint2 p;
        p.x = h22u(__floats2half2_rn(t[0], t[1]));
        p.y = h22u(__floats2half2_rn(t[2], t[3]));
        *(uint2*)(smw + (q + 32 * j) * SLOT_W + 8 * n) = p;
    }
    __syncwarp();

    // ================= conv layer 2 (Cin=4 -> Cout=8) =================
    __half2 acc2[GPT][2];
#pragma unroll
    for (int j = 0; j < GPT; j++) {
        __half2 s0 = __float2half2_rn(0.f), s1 = s0;
        const unsigned* hg = smw + (q + 32 * j) * SLOT_W;
#pragma unroll
        for (int m = 0; m < 8; m++) {
            __half2 cw = (m < 4) ? cnt2(c0[j], m) : cnt2(c1[j], m - 4);
            uint2 v = *(const uint2*)(hg + 8 * m);
            s0 = __hfma2(cw, u2h2(v.x), s0);
            s1 = __hfma2(cw, u2h2(v.y), s1);
        }
        acc2[j][0] = s0; acc2[j][1] = s1;
    }
    __syncwarp();

#pragma unroll
    for (int j = 0; j < GPT; j++) {
        float2 a01 = __half22float2(acc2[j][0]);
        float2 a23 = __half22float2(acc2[j][1]);
        u64 ab[4] = { pack2(a01.x, a01.x), pack2(a01.y, a01.y),
                      pack2(a23.x, a23.x), pack2(a23.y, a23.y) };
        u64 dd = pack2(dis[j], dis[j]);
        unsigned pw[4];
#pragma unroll
        for (int cp = 0; cp < 4; cp++) {
            u64 s = 0ull;
#pragma unroll
            for (int k = 0; k < 4; k++)
                s = fma2(*(const u64*)&cwS[CW_W2 + cp * 8 + 2 * k], ab[k], s);
            s = fma2(dd, s, *(const u64*)&cwS[CW_B2 + 2 * cp]);
            float2 f = unpack2(s);
            pw[cp] = h22u(__floats2half2_rn(fmaxf(f.x, 0.f) * dis[j],
                                            fmaxf(f.y, 0.f) * dis[j]));
        }
        *(uint4*)(smw + (q + 32 * j) * SLOT_W + 8 * n) =
            make_uint4(pw[0], pw[1], pw[2], pw[3]);
    }
    __syncwarp();

    // ================= conv layer 3 (Cin=8 -> Cout=16) via mma =================
    __half2 acc3[GPT][4];
#pragma unroll
    for (int j = 0; j < GPT; j++) {
        __half2 s0 = __float2half2_rn(0.f), s1 = s0, s2 = s0, s3 = s0;
        const unsigned* hg = smw + (q + 32 * j) * SLOT_W;
#pragma unroll
        for (int m = 0; m < 8; m++) {
            __half2 cw = (m < 4) ? cnt2(c0[j], m) : cnt2(c1[j], m - 4);
            uint4 v = *(const uint4*)(hg + 8 * m);
            s0 = __hfma2(cw, u2h2(v.x), s0);
            s1 = __hfma2(cw, u2h2(v.y), s1);
            s2 = __hfma2(cw, u2h2(v.z), s2);
            s3 = __hfma2(cw, u2h2(v.w), s3);
        }
        acc3[j][0] = s0; acc3[j][1] = s1; acc3[j][2] = s2; acc3[j][3] = s3;
    }
    __syncwarp();

    // scale by dis (fp16, per-row = per-thread) and store A operand (4 words/graph)
#pragma unroll
    for (int j = 0; j < GPT; j++) {
        __half2 d2 = __float2half2_rn(dis[j]);
        uint4 st;
        st.x = h22u(__hmul2(acc3[j][0], d2));
        st.y = h22u(__hmul2(acc3[j][1], d2));
        st.z = h22u(__hmul2(acc3[j][2], d2));
        st.w = h22u(__hmul2(acc3[j][3], d2));
        *(uint4*)(smw + (q + 32 * j) * SLOT_W + 8 * n) = st;
    }
    __syncwarp();

    // mma over the warp's 16 graphs: 8 M-tiles (2 graphs each) x 2 N-tiles
    {
        const int grp = lane >> 2;   // 0..7 (= node / output row within tile)
        const int qd  = lane & 3;    // 0..3 (= k-word / channel-pair)
        unsigned b0 = smw[SM_W3H + grp * 4 + qd];        // B cols 0..7  (W3 rows grp)
        unsigned b1 = smw[SM_W3H + (grp + 8) * 4 + qd];  // B cols 8..15
        const float bA0 = cwS[CW_B3 + 2 * qd],     bA1 = cwS[CW_B3 + 2 * qd + 1];
        const float bB0 = cwS[CW_B3 + 8 + 2 * qd], bB1 = cwS[CW_B3 + 9 + 2 * qd];
#pragma unroll
        for (int t = 0; t < 8; t++) {
            int g16a = 2 * t, g16b = 2 * t + 1;              // warp-local graph ids
            int s0 = 4 * w + (g16a & 3) + 32 * (g16a >> 2);  // slot indices
            int s1 = 4 * w + (g16b & 3) + 32 * (g16b >> 2);
            unsigned a0 = smw[s0 * SLOT_W + 8 * grp + qd];   // row grp   (graph g16a)
            unsigned a1 = smw[s1 * SLOT_W + 8 * grp + qd];   // row grp+8 (graph g16b)
            float e0[4] = { bA0, bA1, bA0, bA1 };
            float e1[4] = { bB0, bB1, bB0, bB1 };
            mma_f16_k8(e0, a0, a1, b0);
            mma_f16_k8(e1, a0, a1, b1);
            smw[s0 * SLOT_W + 8 * grp + qd] =
                h22u(__floats2half2_rn(fmaxf(e0[0], 0.f), fmaxf(e0[1], 0.f)));
            smw[s0 * SLOT_W + 8 * grp + 4 + qd] =
                h22u(__floats2half2_rn(fmaxf(e1[0], 0.f), fmaxf(e1[1], 0.f)));
            smw[s1 * SLOT_W + 8 * grp + qd] =
                h22u(__floats2half2_rn(fmaxf(e0[2], 0.f), fmaxf(e0[3], 0.f)));
            smw[s1 * SLOT_W + 8 * grp + 4 + qd] =
                h22u(__floats2half2_rn(fmaxf(e1[2], 0.f), fmaxf(e1[3], 0.f)));
        }
    }

    __syncthreads();   // flat published; Wl1/Wl2 staged

    // ======== MLP1 via fp16 mma m16n8k16: warp w owns slots [16w, 16w+16)
    const int grp = lane >> 2;   // 0..7
    const int qd  = lane & 3;    // 0..3
    const unsigned* aBase = smw + (16 * w + grp) * SLOT_W + qd;
    const unsigned* bBase = smw + SM_W1 + grp * W1_W + qd;

    float d[8][4];
#pragma unroll
    for (int nt = 0; nt < 8; nt++) {
        float cc0 = cwS[CW_BL1 + nt * 8 + 2 * qd], cc1 = cwS[CW_BL1 + nt * 8 + 2 * qd + 1];
        d[nt][0] = cc0; d[nt][1] = cc1; d[nt][2] = cc0; d[nt][3] = cc1;
    }
#pragma unroll
    for (int kc = 0; kc < 8; kc++) {
        unsigned a0 = aBase[kc * 8];
        unsigned a1 = aBase[8 * SLOT_W + kc * 8];
        unsigned a2 = aBase[kc * 8 + 4];
        unsigned a3 = aBase[8 * SLOT_W + kc * 8 + 4];
#pragma unroll
        for (int nt = 0; nt < 8; nt++) {
            unsigned b0 = bBase[nt * 8 * W1_W + kc * 8];
            unsigned b1 = bBase[nt * 8 * W1_W + kc * 8 + 4];
            mma_f16(d[nt], a0, a1, a2, a3, b0, b1);
        }
    }
    __syncwarp();   // flat reads done before z overwrites slot words 0..31

    // relu + store z as halfs (64 halfs = words 0..31 of own slots)
    unsigned* z0 = smw + (16 * w + grp) * SLOT_W;
    unsigned* z1 = z0 + 8 * SLOT_W;
#pragma unroll
    for (int nt = 0; nt < 8; nt++) {
        z0[nt * 4 + qd] = h22u(__floats2half2_rn(fmaxf(d[nt][0], 0.f), fmaxf(d[nt][1], 0.f)));
        z1[nt * 4 + qd] = h22u(__floats2half2_rn(fmaxf(d[nt][2], 0.f), fmaxf(d[nt][3], 0.f)));
    }
    __syncwarp();

    // ======== MLP2 via fp16 mma: A = Z[16x64], B = Wl2[16x64]
    float e[2][4];
#pragma unroll
    for (int nt = 0; nt < 2; nt++) {
        float cc0 = cwS[CW_BL2 + nt * 8 + 2 * qd], cc1 = cwS[CW_BL2 + nt * 8 + 2 * qd + 1];
        e[nt][0] = cc0; e[nt][1] = cc1; e[nt][2] = cc0; e[nt][3] = cc1;
    }
    const unsigned* b2Base = smw + SM_W2 + grp * W2_W + qd;
#pragma unroll
    for (int kc = 0; kc < 4; kc++) {
        unsigned a0 = z0[kc * 8 + qd];
        unsigned a1 = z1[kc * 8 + qd];
        unsigned a2 = z0[kc * 8 + qd + 4];
        unsigned a3 = z1[kc * 8 + qd + 4];
#pragma unroll
        for (int nt = 0; nt < 2; nt++) {
            unsigned b0 = b2Base[nt * 8 * W2_W + kc * 8];
            unsigned b1 = b2Base[nt * 8 * W2_W + kc * 8 + 4];
            mma_f16(e[nt], a0, a1, a2, a3, b0, b1);
        }
    }
    // D fragments -> gmem (coalesced float2)
    const int g0 = gbase + 16 * w + grp;
#pragma unroll
    for (int nt = 0; nt < 2; nt++) {
        int col = nt * 8 + 2 * qd;
        if (g0 < B)
            *(float2*)(out + g0 * 16 + col) = make_float2(e[nt][0], e[nt][1]);
        if (g0 + 8 < B)
            *(float2*)(out + (g0 + 8) * 16 + col) = make_float2(e[nt][2], e[nt][3]);
    }
}

extern "C" void kernel_launch(void* const* d_in, const int* in_sizes, int n_in,
                              void* d_out, int out_size)
{
    const int B = in_sizes[0] / 16;   // x is [B, 8, 2]
    const int grid = (B + GPB - 1) / GPB;

    cudaFuncSetAttribute(gnn_kernel, cudaFuncAttributeMaxDynamicSharedMemorySize, SMEM_BYTES);
    gnn_kernel<<<grid, NTHREADS, SMEM_BYTES>>>(
        (const float*)d_in[0], (const int*)d_in[1],
        (const float*)d_in[8], (const float*)d_in[10],
        (const float*)d_in[6],
        (const float*)d_in[2], (const float*)d_in[3],
        (const float*)d_in[4], (const float*)d_in[5],
        (const float*)d_in[7],
        (const float*)d_in[9], (const float*)d_in[11],
        (float*)d_out, B);
}

// round 17
// speedup vs baseline: 1.0624x; 1.0566x over previous
#include <cuda_runtime.h>
#include <cuda_fp16.h>

#define NTHREADS 256
#define GPB 128           // graphs per block
#define GPT 4             // graphs per thread (conv phase)

#define SLOT_W 68         // 32-bit words per graph slot (128 halfs + pad)
#define W1_W 68           // words per Wl1 row
#define W2_W 36           // words per Wl2 row

// smem layout in 32-bit words. Edges + conv features + flat + z all live in HS slots.
#define SM_HS 0
#define SM_W1 (GPB * SLOT_W)              // 8704
#define SM_W2 (SM_W1 + 64 * W1_W)         // 13056
#define SM_W3H (SM_W2 + 16 * W2_W)        // 13632  (W3 as fp16: 64 words, pos = c*4 + kw)
#define SM_CW (SM_W3H + 64)               // 13696  (small weights, float region)
#define SMEM_WORDS (SM_CW + 288)          // 13984
#define SMEM_BYTES (SMEM_WORDS * 4)       // 55936 B -> 3 blocks/SM

// offsets within CW (floats). W1/W2 segments hold PAIR-TRANSPOSED layout:
//   pos = cp*(2*K) + k*2 + r  <=>  W[(2*cp + r)][k]
#define CW_W1 0
#define CW_B1 8
#define CW_W2 12
#define CW_B2 44
#define CW_B3 180
#define CW_BL1 196
#define CW_BL2 260

typedef unsigned long long u64;

__device__ __forceinline__ u64 fma2(u64 a, u64 b, u64 c) {
    u64 d;
    asm("fma.rn.f32x2 %0, %1, %2, %3;" : "=l"(d) : "l"(a), "l"(b), "l"(c));
    return d;
}
__device__ __forceinline__ u64 pack2(float lo, float hi) {
    u64 d; asm("mov.b64 %0, {%1, %2};" : "=l"(d) : "f"(lo), "f"(hi)); return d;
}
__device__ __forceinline__ float2 unpack2(u64 v) {
    float2 r; asm("mov.b64 {%0, %1}, %2;" : "=f"(r.x), "=f"(r.y) : "l"(v)); return r;
}
__device__ __forceinline__ __half2 u2h2(unsigned u) { return *(__half2*)&u; }
__device__ __forceinline__ unsigned h22u(__half2 h) { return *(unsigned*)&h; }

// count byte (0..16) -> broadcast half2
__device__ __forceinline__ __half2 cnt2(unsigned wd, int m) {
    unsigned b = (wd >> (8 * m)) & 0xFFu;
    return __half2half2(__ushort2half_rn((unsigned short)b));
}

// fp16 mma m16n8k16: D(16x8,f32) += A(16x16,f16) * B(16x8,f16)
__device__ __forceinline__ void mma_f16(float d[4],
    unsigned a0, unsigned a1, unsigned a2, unsigned a3,
    unsigned b0, unsigned b1)
{
    asm("mma.sync.aligned.m16n8k16.row.col.f32.f16.f16.f32 "
        "{%0,%1,%2,%3}, {%4,%5,%6,%7}, {%8,%9}, {%0,%1,%2,%3};"
        : "+f"(d[0]), "+f"(d[1]), "+f"(d[2]), "+f"(d[3])
        : "r"(a0), "r"(a1), "r"(a2), "r"(a3), "r"(b0), "r"(b1));
}
// fp16 mma m16n8k8: D(16x8,f32) += A(16x8,f16) * B(8x8,f16)
__device__ __forceinline__ void mma_f16_k8(float d[4],
    unsigned a0, unsigned a1, unsigned b0)
{
    asm("mma.sync.aligned.m16n8k8.row.col.f32.f16.f16.f32 "
        "{%0,%1,%2,%3}, {%4,%5}, {%6}, {%0,%1,%2,%3};"
        : "+f"(d[0]), "+f"(d[1]), "+f"(d[2]), "+f"(d[3])
        : "r"(a0), "r"(a1), "r"(b0));
}

__global__ __launch_bounds__(NTHREADS, 3)
void gnn_kernel(const float* __restrict__ x, const int* __restrict__ ei,
                const float* __restrict__ Wl1, const float* __restrict__ Wl2,
                const float* __restrict__ W3g,
                const float* __restrict__ W1g, const float* __restrict__ b1g,
                const float* __restrict__ W2g, const float* __restrict__ b2g,
                const float* __restrict__ b3g,
                const float* __restrict__ bl1g, const float* __restrict__ bl2g,
                float* __restrict__ out, int B)
{
    extern __shared__ float smf[];
    unsigned* smw = (unsigned*)smf;
    float* cwS = smf + SM_CW;

    const int tid  = threadIdx.x;
    const int q    = tid >> 3;     // slot 0..31 (conv phase; +32j for graph j)
    const int n    = tid & 7;      // node 0..7
    const int lane = tid & 31;
    const int w    = tid >> 5;     // warp 0..7
    const int gbase = blockIdx.x * GPB;

    // ---- stage small weights/biases (pair-transposed W1/W2) into CW
    if (tid < 8) {                      // W1: 4x2, K=2 -> pair-transposed
        int cp = tid >> 2, rm = tid & 3, k = rm >> 1, r = rm & 1;
        cwS[CW_W1 + tid] = W1g[(2 * cp + r) * 2 + k];
    }
    if (tid >= 8 && tid < 12)   cwS[CW_B1 + tid - 8]  = b1g[tid - 8];
    if (tid >= 32 && tid < 64) {        // W2: 8x4, K=4 -> pair-transposed
        int u = tid - 32, cp = u >> 3, rm = u & 7, k = rm >> 1, r = rm & 1;
        cwS[CW_W2 + u] = W2g[(2 * cp + r) * 4 + k];
    }
    if (tid >= 64 && tid < 72)  cwS[CW_B2 + tid - 64]  = b2g[tid - 64];
    if (tid >= 96 && tid < 112) cwS[CW_B3 + tid - 96]  = b3g[tid - 96];
    if (tid >= 128 && tid < 192) cwS[CW_BL1 + tid - 128] = bl1g[tid - 128];
    if (tid >= 192 && tid < 208) cwS[CW_BL2 + tid - 192] = bl2g[tid - 192];

    // ---- stage Wl1/Wl2 as fp16
#pragma unroll
    for (int i = 0; i < 8; i++) {
        int idx = tid + i * NTHREADS;           // 0..2047 float4s of Wl1 (64x128)
        int r = idx >> 5, kk = idx & 31;
        float4 v = ((const float4*)Wl1)[r * 32 + kk];
        uint2 p;
        p.x = h22u(__floats2half2_rn(v.x, v.y));
        p.y = h22u(__floats2half2_rn(v.z, v.w));
        *(uint2*)(smw + SM_W1 + r * W1_W + 2 * kk) = p;
    }
    {
        int r = tid >> 4, kk = tid & 15;        // Wl2 16x64
        float4 v = ((const float4*)Wl2)[r * 16 + kk];
        uint2 p;
        p.x = h22u(__floats2half2_rn(v.x, v.y));
        p.y = h22u(__floats2half2_rn(v.z, v.w));
        *(uint2*)(smw + SM_W2 + r * W2_W + 2 * kk) = p;
    }
    // ---- stage W3 as fp16 for conv-3 mma: pos = c*4 + kw
    if (tid < 32) {
        float4 v = ((const float4*)W3g)[tid];      // W3[c][4ks..4ks+3], c=tid>>1, ks=tid&1
        int c = tid >> 1, ks = tid & 1;
        smw[SM_W3H + c * 4 + 2 * ks]     = h22u(__floats2half2_rn(v.x, v.y));
        smw[SM_W3H + c * 4 + 2 * ks + 1] = h22u(__floats2half2_rn(v.z, v.w));
    }

    // ---- stage edges WARP-LOCALLY into own slots (stride SLOT_W ints)
    int* esI = (int*)smw;
#pragma unroll
    for (int j = 0; j < GPT; j++) {
        int slot = 4 * w + (lane >> 3) + 32 * j;
        int g = gbase + slot; if (g >= B) g = B - 1;
        int v = lane & 7;
        *(int4*)(esI + slot * SLOT_W + v * 4) = ((const int4*)ei)[g * 8 + v];
    }
    // ---- load x for my graphs
    float h0[GPT][2];
#pragma unroll
    for (int j = 0; j < GPT; j++) {
        int g = gbase + q + 32 * j; if (g >= B) g = B - 1;
        float2 xv = ((const float2*)x)[g * 8 + n];
        h0[j][0] = xv.x; h0[j][1] = xv.y;
    }
    __syncthreads();   // CW + W3h staged, visible to all warps

    // ---- adjacency byte-counts (self-loop folded) + degree (warp-local reads)
    unsigned c0[GPT], c1[GPT]; float dis[GPT];
#pragma unroll
    for (int j = 0; j < GPT; j++) {
        const int4* eg = (const int4*)(esI + (q + 32 * j) * SLOT_W);
        unsigned a0 = 0, a1 = 0;
#pragma unroll
        for (int e4 = 0; e4 < 4; e4++) {
            int4 rv = eg[e4];        // rows
            int4 cv = eg[4 + e4];    // cols
            {unsigned inc = (unsigned)(cv.x == n) << (8 * (rv.x & 3)); if (rv.x < 4) a0 += inc; else a1 += inc;}
            {unsigned inc = (unsigned)(cv.y == n) << (8 * (rv.y & 3)); if (rv.y < 4) a0 += inc; else a1 += inc;}
            {unsigned inc = (unsigned)(cv.z == n) << (8 * (rv.z & 3)); if (rv.z < 4) a0 += inc; else a1 += inc;}
            {unsigned inc = (unsigned)(cv.w == n) << (8 * (rv.w & 3)); if (rv.w < 4) a0 += inc; else a1 += inc;}
        }
        if (n < 4) a0 += 1u << (8 * n); else a1 += 1u << (8 * (n - 4));
        unsigned deg = __dp4a(a0, 0x01010101u, __dp4a(a1, 0x01010101u, 0u));
        dis[j] = rsqrtf((float)deg);
        c0[j] = a0; c1[j] = a1;
    }
    __syncwarp();    // edge reads done before publishes overwrite the slot words

    // ================= conv layer 1 (Cin=2 -> Cout=4) =================
#pragma unroll
    for (int j = 0; j < GPT; j++)
        smw[(q + 32 * j) * SLOT_W + 8 * n] =
            h22u(__floats2half2_rn(h0[j][0] * dis[j], h0[j][1] * dis[j]));
    __syncwarp();

    __half2 acc1[GPT];
#pragma unroll
    for (int j = 0; j < GPT; j++) {
        __half2 acc = __float2half2_rn(0.f);
        const unsigned* hg = smw + (q + 32 * j) * SLOT_W;
#pragma unroll
        for (int m = 0; m < 8; m++) {
            __half2 cw = (m < 4) ? cnt2(c0[j], m) : cnt2(c1[j], m - 4);
            acc = __hfma2(cw, u2h2(hg[8 * m]), acc);
        }
        acc1[j] = acc;
    }
    __syncwarp();

    // matmul W1 (packed f32x2 pairs) + bias + relu + *dis, publish h1*dis
#pragma unroll
    for (int j = 0; j < GPT; j++) {
        float2 a = __half22float2(acc1[j]);
        u64 axx = pack2(a.x, a.x), ayy = pack2(a.y, a.y);
        u64 dd  = pack2(dis[j], dis[j]);
        float t[4];
#pragma unroll
        for (int cp = 0; cp < 2; cp++) {
            u64 s = fma2(*(const u64*)&cwS[CW_W1 + cp * 4], axx, 0ull);
            s = fma2(*(const u64*)&cwS[CW_W1 + cp * 4 + 2], ayy, s);
            s = fma2(dd, s, *(const u64*)&cwS[CW_B1 + 2 * cp]);
            float2 f = unpack2(s);
            t[2 * cp]     = fmaxf(f.x, 0.f) * dis[j];
            t[2 * cp + 1] = fmaxf(f.y, 0.f) * dis[j];
        }
        uint2 p;
        p.x = h22u(__floats2half2_rn(t[0], t[1]));
        p.y = h22u(__floats2half2_rn(t[2], t[3]));
        *(uint2*)(smw + (q + 32 * j) * SLOT_W + 8 * n) = p;
    }
    __syncwarp();

    // ================= conv layer 2 (Cin=4 -> Cout=8) =================
    __half2 acc2[GPT][2];
#pragma unroll
    for (int j = 0; j < GPT; j++) {
        __half2 s0 = __float2half2_rn(0.f), s1 = s0;
        const unsigned* hg = smw + (q + 32 * j) * SLOT_W;
#pragma unroll
        for (int m = 0; m < 8; m++) {
            __half2 cw = (m < 4) ? cnt2(c0[j], m) : cnt2(c1[j], m - 4);
            uint2 v = *(const uint2*)(hg + 8 * m);
            s0 = __hfma2(cw, u2h2(v.x), s0);
            s1 = __hfma2(cw, u2h2(v.y), s1);
        }
        acc2[j][0] = s0; acc2[j][1] = s1;
    }
    __syncwarp();

#pragma unroll
    for (int j = 0; j < GPT; j++) {
        float2 a01 = __half22float2(acc2[j][0]);
        float2 a23 = __half22float2(acc2[j][1]);
        u64 ab[4] = { pack2(a01.x, a01.x), pack2(a01.y, a01.y),
                      pack2(a23.x, a23.x), pack2(a23.y, a23.y) };
        u64 dd = pack2(dis[j], dis[j]);
        unsigned pw[4];
#pragma unroll
        for (int cp = 0; cp < 4; cp++) {
            u64 s = 0ull;
#pragma unroll
            for (int k = 0; k < 4; k++)
                s = fma2(*(const u64*)&cwS[CW_W2 + cp * 8 + 2 * k], ab[k], s);
            s = fma2(dd, s, *(const u64*)&cwS[CW_B2 + 2 * cp]);
            float2 f = unpack2(s);
            pw[cp] = h22u(__floats2half2_rn(fmaxf(f.x, 0.f) * dis[j],
                                            fmaxf(f.y, 0.f) * dis[j]));
        }
        *(uint4*)(smw + (q + 32 * j) * SLOT_W + 8 * n) =
            make_uint4(pw[0], pw[1], pw[2], pw[3]);
    }
    __syncwarp();

    // ================= conv layer 3 (Cin=8 -> Cout=16) via mma =================
    __half2 acc3[GPT][4];
#pragma unroll
    for (int j = 0; j < GPT; j++) {
        __half2 s0 = __float2half2_rn(0.f), s1 = s0, s2 = s0, s3 = s0;
        const unsigned* hg = smw + (q + 32 * j) * SLOT_W;
#pragma unroll
        for (int m = 0; m < 8; m++) {
            __half2 cw = (m < 4) ? cnt2(c0[j], m) : cnt2(c1[j], m - 4);
            uint4 v = *(const uint4*)(hg + 8 * m);
            s0 = __hfma2(cw, u2h2(v.x), s0);
            s1 = __hfma2(cw, u2h2(v.y), s1);
            s2 = __hfma2(cw, u2h2(v.z), s2);
            s3 = __hfma2(cw, u2h2(v.w), s3);
        }
        acc3[j][0] = s0; acc3[j][1] = s1; acc3[j][2] = s2; acc3[j][3] = s3;
    }
    __syncwarp();

    // scale by dis (fp16, per-row = per-thread) and store A operand (4 words/graph)
#pragma unroll
    for (int j = 0; j < GPT; j++) {
        __half2 d2 = __float2half2_rn(dis[j]);
        uint4 st;
        st.x = h22u(__hmul2(acc3[j][0], d2));
        st.y = h22u(__hmul2(acc3[j][1], d2));
        st.z = h22u(__hmul2(acc3[j][2], d2));
        st.w = h22u(__hmul2(acc3[j][3], d2));
        *(uint4*)(smw + (q + 32 * j) * SLOT_W + 8 * n) = st;
    }
    __syncwarp();

    // mma over the warp's 16 graphs: 8 M-tiles (2 graphs each) x 2 N-tiles
    {
        const int grp = lane >> 2;   // 0..7 (= node / output row within tile)
        const int qd  = lane & 3;    // 0..3 (= k-word / channel-pair)
        unsigned b0 = smw[SM_W3H + grp * 4 + qd];        // B cols 0..7  (W3 rows grp)
        unsigned b1 = smw[SM_W3H + (grp + 8) * 4 + qd];  // B cols 8..15
        const float bA0 = cwS[CW_B3 + 2 * qd],     bA1 = cwS[CW_B3 + 2 * qd + 1];
        const float bB0 = cwS[CW_B3 + 8 + 2 * qd], bB1 = cwS[CW_B3 + 9 + 2 * qd];
#pragma unroll
        for (int t = 0; t < 8; t++) {
            int g16a = 2 * t, g16b = 2 * t + 1;              // warp-local graph ids
            int s0 = 4 * w + (g16a & 3) + 32 * (g16a >> 2);  // slot indices
            int s1 = 4 * w + (g16b & 3) + 32 * (g16b >> 2);
            unsigned a0 = smw[s0 * SLOT_W + 8 * grp + qd];   // row grp   (graph g16a)
            unsigned a1 = smw[s1 * SLOT_W + 8 * grp + qd];   // row grp+8 (graph g16b)
            float e0[4] = { bA0, bA1, bA0, bA1 };
            float e1[4] = { bB0, bB1, bB0, bB1 };
            mma_f16_k8(e0, a0, a1, b0);
            mma_f16_k8(e1, a0, a1, b1);
            smw[s0 * SLOT_W + 8 * grp + qd] =
                h22u(__floats2half2_rn(fmaxf(e0[0], 0.f), fmaxf(e0[1], 0.f)));
            smw[s0 * SLOT_W + 8 * grp + 4 + qd] =
                h22u(__floats2half2_rn(fmaxf(e1[0], 0.f), fmaxf(e1[1], 0.f)));
            smw[s1 * SLOT_W + 8 * grp + qd] =
                h22u(__floats2half2_rn(fmaxf(e0[2], 0.f), fmaxf(e0[3], 0.f)));
            smw[s1 * SLOT_W + 8 * grp + 4 + qd] =
                h22u(__floats2half2_rn(fmaxf(e1[2], 0.f), fmaxf(e1[3], 0.f)));
        }
    }

    __syncthreads();   // flat published; weights staged

    // ======== MLP1 via fp16 mma m16n8k16, RE-TILED m=2 x n=4:
    // warp w -> M-pair mp = w&3 (slots 32mp..32mp+31), N-tiles nb..nb+3 (nb = 4*(w>>2))
    const int grp = lane >> 2;   // 0..7
    const int qd  = lane & 3;    // 0..3
    const int mp = w & 3;
    const int nb = (w >> 2) * 4;
    const unsigned* aB0 = smw + (32 * mp + grp) * SLOT_W + qd;        // M-tile 2mp
    const unsigned* aB1 = smw + (32 * mp + 16 + grp) * SLOT_W + qd;   // M-tile 2mp+1
    const unsigned* bBase = smw + SM_W1 + grp * W1_W + qd;

    float d[2][4][4];
#pragma unroll
    for (int mt = 0; mt < 2; mt++)
#pragma unroll
        for (int nt = 0; nt < 4; nt++) {
            float cc0 = cwS[CW_BL1 + (nb + nt) * 8 + 2 * qd];
            float cc1 = cwS[CW_BL1 + (nb + nt) * 8 + 2 * qd + 1];
            d[mt][nt][0] = cc0; d[mt][nt][1] = cc1;
            d[mt][nt][2] = cc0; d[mt][nt][3] = cc1;
        }
#pragma unroll
    for (int kc = 0; kc < 8; kc++) {
        unsigned a00 = aB0[kc * 8];
        unsigned a01 = aB0[8 * SLOT_W + kc * 8];
        unsigned a02 = aB0[kc * 8 + 4];
        unsigned a03 = aB0[8 * SLOT_W + kc * 8 + 4];
        unsigned a10 = aB1[kc * 8];
        unsigned a11 = aB1[8 * SLOT_W + kc * 8];
        unsigned a12 = aB1[kc * 8 + 4];
        unsigned a13 = aB1[8 * SLOT_W + kc * 8 + 4];
#pragma unroll
        for (int nt = 0; nt < 4; nt++) {
            unsigned b0 = bBase[(nb + nt) * 8 * W1_W + kc * 8];
            unsigned b1 = bBase[(nb + nt) * 8 * W1_W + kc * 8 + 4];
            mma_f16(d[0][nt], a00, a01, a02, a03, b0, b1);
            mma_f16(d[1][nt], a10, a11, a12, a13, b0, b1);
        }
    }
    __syncthreads();   // ALL warps' flat reads done before any z store

    // relu + store z: slot group 32mp+16mt, words (nb+nt)*4+qd (disjoint across warps)
#pragma unroll
    for (int mt = 0; mt < 2; mt++) {
        unsigned* zz0 = smw + (32 * mp + 16 * mt + grp) * SLOT_W;
        unsigned* zz1 = zz0 + 8 * SLOT_W;
#pragma unroll
        for (int nt = 0; nt < 4; nt++) {
            int pos = (nb + nt) * 4 + qd;
            zz0[pos] = h22u(__floats2half2_rn(fmaxf(d[mt][nt][0], 0.f), fmaxf(d[mt][nt][1], 0.f)));
            zz1[pos] = h22u(__floats2half2_rn(fmaxf(d[mt][nt][2], 0.f), fmaxf(d[mt][nt][3], 0.f)));
        }
    }
    __syncthreads();   // z complete (cross-warp) before MLP2 reads

    // ======== MLP2 via fp16 mma: warp w owns slots [16w, 16w+16) (unchanged)
    unsigned* z0 = smw + (16 * w + grp) * SLOT_W;
    unsigned* z1 = z0 + 8 * SLOT_W;
    float e[2][4];
#pragma unroll
    for (int nt = 0; nt < 2; nt++) {
        float cc0 = cwS[CW_BL2 + nt * 8 + 2 * qd], cc1 = cwS[CW_BL2 + nt * 8 + 2 * qd + 1];
        e[nt][0] = cc0; e[nt][1] = cc1; e[nt][2] = cc0; e[nt][3] = cc1;
    }
    const unsigned* b2Base = smw + SM_W2 + grp * W2_W + qd;
#pragma unroll
    for (int kc = 0; kc < 4; kc++) {
        unsigned a0 = z0[kc * 8 + qd];
        unsigned a1 = z1[kc * 8 + qd];
        unsigned a2 = z0[kc * 8 + qd + 4];
        unsigned a3 = z1[kc * 8 + qd + 4];
#pragma unroll
        for (int nt = 0; nt < 2; nt++) {
            unsigned b0 = b2Base[nt * 8 * W2_W + kc * 8];
            unsigned b1 = b2Base[nt * 8 * W2_W + kc * 8 + 4];
            mma_f16(e[nt], a0, a1, a2, a3, b0, b1);
        }
    }
    // D fragments -> gmem (coalesced float2)
    const int g0 = gbase + 16 * w + grp;
#pragma unroll
    for (int nt = 0; nt < 2; nt++) {
        int col = nt * 8 + 2 * qd;
        if (g0 < B)
            *(float2*)(out + g0 * 16 + col) = make_float2(e[nt][0], e[nt][1]);
        if (g0 + 8 < B)
            *(float2*)(out + (g0 + 8) * 16 + col) = make_float2(e[nt][2], e[nt][3]);
    }
}

extern "C" void kernel_launch(void* const* d_in, const int* in_sizes, int n_in,
                              void* d_out, int out_size)
{
    const int B = in_sizes[0] / 16;   // x is [B, 8, 2]
    const int grid = (B + GPB - 1) / GPB;

    cudaFuncSetAttribute(gnn_kernel, cudaFuncAttributeMaxDynamicSharedMemorySize, SMEM_BYTES);
    gnn_kernel<<<grid, NTHREADS, SMEM_BYTES>>>(
        (const float*)d_in[0], (const int*)d_in[1],
        (const float*)d_in[8], (const float*)d_in[10],
        (const float*)d_in[6],
        (const float*)d_in[2], (const float*)d_in[3],
        (const float*)d_in[4], (const float*)d_in[5],
        (const float*)d_in[7],
        (const float*)d_in[9], (const float*)d_in[11],
        (float*)d_out, B);
}